// round 10
// baseline (speedup 1.0000x reference)
#include <cuda_runtime.h>
#include <cstdint>

// GCNDecoder: x' = relu(LN(Ahat^T (x W_conv) + b_conv) W_mlp + b_mlp)) x3, then x W_lin + b_lin
// N=8192 nodes, H=512 features, 3 layers, O=512.

#define NND   8192
#define HH    512
#define CHUNKS 16
#define RPC   (NND / CHUNKS)     // 512 rows per chunk
#define MAXNNZ (1 << 22)         // 4M entries, data has ~550K
#define CAP   32                 // compaction capacity per (chunk,col) cell

#define WMAT  (HH * HH)          // 262144 elements per weight matrix
#define W_CONV_OFF 0
#define W_MLP_OFF  (3 * WMAT)
#define W_LIN_OFF  (6 * WMAT)

// ---------------- device scratch (no allocations allowed) ----------------
__device__ float g_dinv[NND];           // deg^-0.5
__device__ float g_selfc[NND];          // sl * dinv^2
__device__ float g_dsum2[CHUNKS * NND]; // per-(chunk,col) column sums of positives
__device__ int   g_cnt2[CHUNKS * NND];  // per-(chunk,col) nnz counts
__device__ int   g_tot[NND];            // per-col nnz totals
__device__ int   g_rowptr[NND + 1];     // CSC row ptr (per output node)
__device__ int   g_choff[CHUNKS * NND]; // per-(chunk,col) fill offsets
__device__ __align__(16) uint2 g_pack[CHUNKS * NND * CAP]; // compacted {row, bits(val)}
__device__ int   g_cols[MAXNNZ];
__device__ float g_vals[MAXNNZ];        // A[s][t] * dinv[s] * dinv[t]
__device__ __align__(16) uint2 g_Wsplit[7 * WMAT];  // weights pre-split {tf32_hi, tf32_lo}
__device__ float g_X[NND * HH];
__device__ float g_Y[NND * HH];
__device__ float g_Z[NND * HH];

// ---------------- tf32 split helpers ----------------

__device__ __forceinline__ void split_tf32(float x, uint32_t& hi, uint32_t& lo) {
    uint32_t h;
    asm("cvt.rna.tf32.f32 %0, %1;" : "=r"(h) : "f"(x));
    float r = x - __uint_as_float(h);
    uint32_t l;
    asm("cvt.rna.tf32.f32 %0, %1;" : "=r"(l) : "f"(r));
    hi = h; lo = l;
}

// pre-split a weight blob into interleaved {hi, lo}
__global__ void wsplit_kernel(const float* __restrict__ src, uint2* __restrict__ dst, int n) {
    int i = blockIdx.x * blockDim.x + threadIdx.x;
    if (i < n) {
        uint32_t h, l;
        split_tf32(src[i], h, l);
        dst[i] = make_uint2(h, l);
    }
}

// ---------------- preprocessing ----------------

// Single pass over A: per-(chunk,col) sums/counts AND compaction of nonzeros.
__global__ void stats_compact_kernel(const float* __restrict__ A) {
    int t = blockIdx.x * 128 + threadIdx.x;   // column
    int c = blockIdx.y;                       // row chunk
    int s0 = c * RPC;
    const float* p = A + (size_t)s0 * NND + t;
    uint2* cell = g_pack + (size_t)(c * NND + t) * CAP;
    float sum = 0.f;
    int cnt = 0;
    for (int i = 0; i < RPC; i++) {
        float v = p[(size_t)i * NND];
        if (v > 0.f) {
            sum += v;
            if (cnt < CAP) cell[cnt] = make_uint2((unsigned)(s0 + i), __float_as_uint(v));
            cnt++;
        }
    }
    g_dsum2[c * NND + t] = sum;
    g_cnt2[c * NND + t] = cnt;
}

// degree -> dinv; also reads the diagonal directly for the self-loop indicator
__global__ void dinv_kernel(const float* __restrict__ A) {
    int t = blockIdx.x * blockDim.x + threadIdx.x;
    if (t >= NND) return;
    float ds = 0.f; int tot = 0;
#pragma unroll
    for (int c = 0; c < CHUNKS; c++) {
        ds += g_dsum2[c * NND + t];
        tot += g_cnt2[c * NND + t];
    }
    float d = A[(size_t)t * NND + t];
    float sl = (d > 0.f) ? 0.f : 1.f;
    float deg = ds + sl;
    float dv = (deg > 0.f) ? rsqrtf(deg) : 0.f;
    g_dinv[t] = dv;
    g_selfc[t] = sl * dv * dv;
    g_tot[t] = tot;
}

// single-block exclusive scan of g_tot[0..8191] -> g_rowptr
__global__ void scan_kernel() {
    int tid = threadIdx.x;            // 1024 threads, 8 elems each
    int base = tid * 8;
    int loc[8]; int s = 0;
#pragma unroll
    for (int i = 0; i < 8; i++) { int v = g_tot[base + i]; loc[i] = s; s += v; }
    int lane = tid & 31, wid = tid >> 5;
    int val = s;
#pragma unroll
    for (int off = 1; off < 32; off <<= 1) {
        int n = __shfl_up_sync(0xffffffffu, val, off);
        if (lane >= off) val += n;
    }
    __shared__ int wsum[32];
    if (lane == 31) wsum[wid] = val;
    __syncthreads();
    if (wid == 0) {
        int w = wsum[lane];
#pragma unroll
        for (int off = 1; off < 32; off <<= 1) {
            int n = __shfl_up_sync(0xffffffffu, w, off);
            if (lane >= off) w += n;
        }
        wsum[lane] = w;
    }
    __syncthreads();
    int warpoff = (wid == 0) ? 0 : wsum[wid - 1];
    int excl = warpoff + (val - s);   // exclusive prefix of this thread
#pragma unroll
    for (int i = 0; i < 8; i++) g_rowptr[base + i] = excl + loc[i];
    if (tid == 1023) g_rowptr[NND] = excl + s;
}

__global__ void choff_kernel() {
    int t = blockIdx.x * blockDim.x + threadIdx.x;
    if (t >= NND) return;
    int run = g_rowptr[t];
#pragma unroll
    for (int c = 0; c < CHUNKS; c++) {
        g_choff[c * NND + t] = run;
        run += g_cnt2[c * NND + t];
    }
}

// fill from compacted scratch; deterministic exclusive [choff, choff+cnt) ranges.
// Rare overflow (cnt > CAP) falls back to re-reading that column strip from A.
__global__ void fill_kernel(const float* __restrict__ A) {
    int t = blockIdx.x * 128 + threadIdx.x;
    int c = blockIdx.y;
    int cell_idx = c * NND + t;
    int cnt = g_cnt2[cell_idx];
    int pos = g_choff[cell_idx];
    float dt = g_dinv[t];
    if (cnt <= CAP) {
        const uint2* cell = g_pack + (size_t)cell_idx * CAP;
        for (int j = 0; j < cnt; j++) {
            uint2 e = cell[j];
            int s = (int)e.x;
            if (pos < MAXNNZ) {
                g_cols[pos] = s;
                g_vals[pos] = __uint_as_float(e.y) * __ldg(&g_dinv[s]) * dt;
            }
            pos++;
        }
    } else {
        int s0 = c * RPC;
        const float* p = A + (size_t)s0 * NND + t;
        for (int i = 0; i < RPC; i++) {
            float v = p[(size_t)i * NND];
            if (v > 0.f) {
                if (pos < MAXNNZ) {
                    int s = s0 + i;
                    g_cols[pos] = s;
                    g_vals[pos] = v * __ldg(&g_dinv[s]) * dt;
                }
                pos++;
            }
        }
    }
}

// ---------------- tensor-core GEMM (3xTF32): C[M x 512] = A[M x 512] @ B[512 x 512] (+bias) ----
// 128x128 block tile, BK=16, 256 threads = 8 warps (2 x 4), warp tile 64x32.
// mma.sync.m16n8k8 tf32, error split: C += Ah*Bh + Ah*Bl + Al*Bh.
// A: raw f32, split at fragment load. B: pre-split {hi,lo} uint2, LDS.64 fragment load.
// DYNAMIC shared memory: [As 2x128x20 f32][Bs 2x16x132 uint2] = 54272 B.
// ONE barrier per K-slab: the top barrier of iteration t proves all warps finished
// compute of slab t-1, which is the only hazard the old bottom barrier guarded.

#define GK 512
#define SA_STR 20    // As[m][k]: (20m+k) mod 32 all distinct across a warp's frag load
#define SB2    132   // Bs[k][n] uint2: per 16-lane phase (4*tig+gid) mod 16 distinct
#define ASLAB  (128 * SA_STR)              // floats per A buffer
#define BSLAB  (16 * SB2)                  // uint2 per B buffer
#define ASZ_B  (2 * ASLAB * 4)             // 20480 bytes
#define BSZ_B  (2 * BSLAB * 8)             // 33792 bytes
#define SMEM_GEMM (ASZ_B + BSZ_B)          // 54272 bytes

__device__ __forceinline__ void mma_tf32(float* c, uint32_t a0, uint32_t a1, uint32_t a2, uint32_t a3,
                                         uint32_t b0, uint32_t b1) {
    asm volatile(
        "mma.sync.aligned.m16n8k8.row.col.f32.tf32.tf32.f32 "
        "{%0,%1,%2,%3}, {%4,%5,%6,%7}, {%8,%9}, {%0,%1,%2,%3};"
        : "+f"(c[0]), "+f"(c[1]), "+f"(c[2]), "+f"(c[3])
        : "r"(a0), "r"(a1), "r"(a2), "r"(a3), "r"(b0), "r"(b1));
}

#define CP_ASYNC16(dst32, src) \
    asm volatile("cp.async.ca.shared.global [%0], [%1], 16;" :: "r"(dst32), "l"(src))
#define CP_COMMIT() asm volatile("cp.async.commit_group;")
#define CP_WAIT0()  asm volatile("cp.async.wait_group 0;")

__global__ __launch_bounds__(256, 2) void gemm_tc_kernel(
    const float* __restrict__ A, const uint2* __restrict__ B2,
    const float* __restrict__ bias, float* __restrict__ C)
{
    extern __shared__ __align__(16) unsigned char smem_raw[];
    float* AsB = (float*)smem_raw;                   // [2][128][SA_STR]
    uint2* BsB = (uint2*)(smem_raw + ASZ_B);         // [2][16][SB2]

    const int tid = threadIdx.x;
    const int lane = tid & 31;
    const int warp = tid >> 5;
    const int gid = lane >> 2;    // 0..7
    const int tig = lane & 3;     // 0..3
    const int wm = warp >> 2;     // 0..1 -> m offset wm*64
    const int wn = warp & 3;      // 0..3 -> n offset wn*32

    const float* Ab = A + (size_t)blockIdx.y * 128 * GK;
    const uint2* Bb = B2 + blockIdx.x * 128;

    // cp.async slot mapping.
    // A: 2 slots x float4 (128x16 f32 tile = 512 float4s over 256 threads)
    int am[2], ak[2];
#pragma unroll
    for (int r = 0; r < 2; r++) {
        int s = tid + r * 256;           // [0,512)
        am[r] = s >> 2;                  // A row in tile [0,128)
        ak[r] = (s & 3) << 2;            // A k offset {0,4,8,12}
    }
    // B: 4 slots x 16B (= 2 uint2 each); 16x128 uint2 tile = 1024 16B-slots
    int bk[4], bn[4];
#pragma unroll
    for (int r = 0; r < 4; r++) {
        int s = tid + r * 256;           // [0,1024)
        bk[r] = s >> 6;                  // B k row [0,16)
        bn[r] = (s & 63) << 1;           // B n offset [0,128) step 2 (even -> 16B aligned)
    }
    uint32_t as_dst[2], bs_dst[4];
#pragma unroll
    for (int r = 0; r < 2; r++)
        as_dst[r] = (uint32_t)__cvta_generic_to_shared(AsB + am[r] * SA_STR + ak[r]);
#pragma unroll
    for (int r = 0; r < 4; r++)
        bs_dst[r] = (uint32_t)__cvta_generic_to_shared(BsB + bk[r] * SB2 + bn[r]);
    const uint32_t aoff1 = (uint32_t)(ASLAB * 4);   // byte offset of A buffer 1
    const uint32_t boff1 = (uint32_t)(BSLAB * 8);   // byte offset of B buffer 1

    float acc[4][4][4];   // [mi][ni][frag]
#pragma unroll
    for (int i = 0; i < 4; i++)
#pragma unroll
        for (int j = 0; j < 4; j++)
#pragma unroll
            for (int q = 0; q < 4; q++) acc[i][j][q] = 0.f;

    // prologue: load slab 0
#pragma unroll
    for (int r = 0; r < 2; r++)
        CP_ASYNC16(as_dst[r], Ab + (size_t)am[r] * GK + ak[r]);
#pragma unroll
    for (int r = 0; r < 4; r++)
        CP_ASYNC16(bs_dst[r], Bb + (size_t)bk[r] * 512 + bn[r]);
    CP_COMMIT();

    const int NT = GK / 16;   // 32 slabs
    for (int t = 0; t < NT; t++) {
        CP_WAIT0();
        __syncthreads();     // slab t data visible to all; all warps done computing slab t-1

        if (t + 1 < NT) {
            int k0 = (t + 1) * 16;
            uint32_t dA = ((t + 1) & 1) ? aoff1 : 0;
            uint32_t dB = ((t + 1) & 1) ? boff1 : 0;
#pragma unroll
            for (int r = 0; r < 2; r++)
                CP_ASYNC16(as_dst[r] + dA, Ab + (size_t)am[r] * GK + k0 + ak[r]);
#pragma unroll
            for (int r = 0; r < 4; r++)
                CP_ASYNC16(bs_dst[r] + dB, Bb + (size_t)(k0 + bk[r]) * 512 + bn[r]);
            CP_COMMIT();
        }

        const float* Asb = AsB + (t & 1) * ASLAB;
        const uint2* Bsb = BsB + (t & 1) * BSLAB;
#pragma unroll
        for (int ks = 0; ks < 2; ks++) {
            const int kb = ks * 8;
            // B fragments: 4 n8 tiles, pre-split hi/lo via single LDS.64 each
            uint32_t bh[4][2], bl[4][2];
#pragma unroll
            for (int ni = 0; ni < 4; ni++) {
                int n = wn * 32 + ni * 8 + gid;
                uint2 p0 = Bsb[(kb + tig) * SB2 + n];
                uint2 p1 = Bsb[(kb + tig + 4) * SB2 + n];
                bh[ni][0] = p0.x; bl[ni][0] = p0.y;
                bh[ni][1] = p1.x; bl[ni][1] = p1.y;
            }
#pragma unroll
            for (int mi = 0; mi < 4; mi++) {
                int m = wm * 64 + mi * 16 + gid;
                float a0f = Asb[m * SA_STR + kb + tig];
                float a1f = Asb[(m + 8) * SA_STR + kb + tig];
                float a2f = Asb[m * SA_STR + kb + tig + 4];
                float a3f = Asb[(m + 8) * SA_STR + kb + tig + 4];
                uint32_t ah[4], al[4];
                split_tf32(a0f, ah[0], al[0]);
                split_tf32(a1f, ah[1], al[1]);
                split_tf32(a2f, ah[2], al[2]);
                split_tf32(a3f, ah[3], al[3]);
#pragma unroll
                for (int ni = 0; ni < 4; ni++) {
                    mma_tf32(acc[mi][ni], ah[0], ah[1], ah[2], ah[3], bh[ni][0], bh[ni][1]);
                    mma_tf32(acc[mi][ni], ah[0], ah[1], ah[2], ah[3], bl[ni][0], bl[ni][1]);
                    mma_tf32(acc[mi][ni], al[0], al[1], al[2], al[3], bh[ni][0], bh[ni][1]);
                }
            }
        }
        // no bottom barrier needed: next iteration's top barrier covers the
        // buffer-reuse hazard (prefetch into (t+1)&1 happens only after it)
    }

    // epilogue (bias hoisted: invariant in mi)
    float bb[4][2];
#pragma unroll
    for (int ni = 0; ni < 4; ni++) {
        int col = wn * 32 + ni * 8 + tig * 2;
        if (bias) {
            bb[ni][0] = bias[blockIdx.x * 128 + col];
            bb[ni][1] = bias[blockIdx.x * 128 + col + 1];
        } else {
            bb[ni][0] = 0.f; bb[ni][1] = 0.f;
        }
    }
    float* Cb = C + (size_t)blockIdx.y * 128 * 512 + blockIdx.x * 128;
#pragma unroll
    for (int mi = 0; mi < 4; mi++) {
#pragma unroll
        for (int ni = 0; ni < 4; ni++) {
            int row0 = wm * 64 + mi * 16 + gid;
            int col = wn * 32 + ni * 8 + tig * 2;
            float2 v0 = { acc[mi][ni][0] + bb[ni][0], acc[mi][ni][1] + bb[ni][1] };
            float2 v1 = { acc[mi][ni][2] + bb[ni][0], acc[mi][ni][3] + bb[ni][1] };
            *(float2*)(Cb + (size_t)row0 * 512 + col) = v0;
            *(float2*)(Cb + (size_t)(row0 + 8) * 512 + col) = v1;
        }
    }
}

// ---------------- SpMM: Out[t] = sum_s vals * Y[s] + selfc[t]*Y[t] + bias ----------------
// warp per output node, 16 f32 accumulators per lane.
// 2-edge unroll, 8 independent LDG.128 in flight; self-row and bias loads
// issued BEFORE the edge loop so their latency overlaps the whole gather loop
// (Y is read-only here; Out is a distinct buffer).

__global__ void spmm_kernel(const float* __restrict__ Y,
                            const float* __restrict__ bias,
                            float* __restrict__ Out)
{
    int gw = (blockIdx.x * blockDim.x + threadIdx.x) >> 5;
    int lane = threadIdx.x & 31;
    if (gw >= NND) return;
    int beg = __ldg(&g_rowptr[gw]), end = __ldg(&g_rowptr[gw + 1]);
    const float4* Y4 = (const float4*)Y;

    // front-issue loop-independent loads (overlap with the edge loop)
    float sc = g_selfc[gw];
    const float4* xr = Y4 + (size_t)gw * 128 + lane;
    float4 s0 = __ldg(xr), s1 = __ldg(xr + 32), s2 = __ldg(xr + 64), s3 = __ldg(xr + 96);
    const float4* b4 = (const float4*)bias;
    float4 b0 = __ldg(b4 + lane), b1 = __ldg(b4 + lane + 32),
           b2 = __ldg(b4 + lane + 64), b3 = __ldg(b4 + lane + 96);

    float4 a0 = {0,0,0,0}, a1 = a0, a2 = a0, a3 = a0;
    int k = beg;
    for (; k + 1 < end; k += 2) {
        int sA = g_cols[k],   sB = g_cols[k + 1];
        float wA = g_vals[k], wB = g_vals[k + 1];
        const float4* yA = Y4 + (size_t)sA * 128 + lane;
        const float4* yB = Y4 + (size_t)sB * 128 + lane;
        float4 u0 = __ldg(yA), u1 = __ldg(yA + 32), u2 = __ldg(yA + 64), u3 = __ldg(yA + 96);
        float4 t0 = __ldg(yB), t1 = __ldg(yB + 32), t2 = __ldg(yB + 64), t3 = __ldg(yB + 96);
        a0.x += wA * u0.x; a0.y += wA * u0.y; a0.z += wA * u0.z; a0.w += wA * u0.w;
        a1.x += wA * u1.x; a1.y += wA * u1.y; a1.z += wA * u1.z; a1.w += wA * u1.w;
        a2.x += wA * u2.x; a2.y += wA * u2.y; a2.z += wA * u2.z; a2.w += wA * u2.w;
        a3.x += wA * u3.x; a3.y += wA * u3.y; a3.z += wA * u3.z; a3.w += wA * u3.w;
        a0.x += wB * t0.x; a0.y += wB * t0.y; a0.z += wB * t0.z; a0.w += wB * t0.w;
        a1.x += wB * t1.x; a1.y += wB * t1.y; a1.z += wB * t1.z; a1.w += wB * t1.w;
        a2.x += wB * t2.x; a2.y += wB * t2.y; a2.z += wB * t2.z; a2.w += wB * t2.w;
        a3.x += wB * t3.x; a3.y += wB * t3.y; a3.z += wB * t3.z; a3.w += wB * t3.w;
    }
    if (k < end) {
        int s = g_cols[k];
        float w = g_vals[k];
        const float4* yr = Y4 + (size_t)s * 128 + lane;
        float4 v0 = __ldg(yr), v1 = __ldg(yr + 32), v2 = __ldg(yr + 64), v3 = __ldg(yr + 96);
        a0.x += w * v0.x; a0.y += w * v0.y; a0.z += w * v0.z; a0.w += w * v0.w;
        a1.x += w * v1.x; a1.y += w * v1.y; a1.z += w * v1.z; a1.w += w * v1.w;
        a2.x += w * v2.x; a2.y += w * v2.y; a2.z += w * v2.z; a2.w += w * v2.w;
        a3.x += w * v3.x; a3.y += w * v3.y; a3.z += w * v3.z; a3.w += w * v3.w;
    }
    a0.x += sc * s0.x + b0.x; a0.y += sc * s0.y + b0.y; a0.z += sc * s0.z + b0.z; a0.w += sc * s0.w + b0.w;
    a1.x += sc * s1.x + b1.x; a1.y += sc * s1.y + b1.y; a1.z += sc * s1.z + b1.z; a1.w += sc * s1.w + b1.w;
    a2.x += sc * s2.x + b2.x; a2.y += sc * s2.y + b2.y; a2.z += sc * s2.z + b2.z; a2.w += sc * s2.w + b2.w;
    a3.x += sc * s3.x + b3.x; a3.y += sc * s3.y + b3.y; a3.z += sc * s3.z + b3.z; a3.w += sc * s3.w + b3.w;
    float4* O4 = (float4*)Out + (size_t)gw * 128 + lane;
    O4[0] = a0; O4[32] = a1; O4[64] = a2; O4[96] = a3;
}

// ---------------- LayerNorm + ReLU (warp per row) ----------------

__global__ void ln_relu_kernel(const float* __restrict__ Xin,
                               const float* __restrict__ g,
                               const float* __restrict__ b,
                               float* __restrict__ Xout)
{
    int gw = (blockIdx.x * blockDim.x + threadIdx.x) >> 5;
    int lane = threadIdx.x & 31;
    if (gw >= NND) return;
    const float4* xr = (const float4*)Xin + (size_t)gw * 128;
    float4 v[4];
    float s = 0.f;
#pragma unroll
    for (int i = 0; i < 4; i++) {
        v[i] = xr[lane + 32 * i];
        s += v[i].x + v[i].y + v[i].z + v[i].w;
    }
#pragma unroll
    for (int off = 16; off; off >>= 1) s += __shfl_xor_sync(0xffffffffu, s, off);
    float mu = s * (1.f / 512.f);
    float var = 0.f;
#pragma unroll
    for (int i = 0; i < 4; i++) {
        float dx = v[i].x - mu, dy = v[i].y - mu, dz = v[i].z - mu, dw = v[i].w - mu;
        var += dx * dx + dy * dy + dz * dz + dw * dw;
    }
#pragma unroll
    for (int off = 16; off; off >>= 1) var += __shfl_xor_sync(0xffffffffu, var, off);
    float rstd = rsqrtf(var * (1.f / 512.f) + 1e-5f);
    const float4* g4 = (const float4*)g;
    const float4* b4 = (const float4*)b;
    float4* o = (float4*)Xout + (size_t)gw * 128;
#pragma unroll
    for (int i = 0; i < 4; i++) {
        float4 gg = g4[lane + 32 * i], bb = b4[lane + 32 * i];
        float4 r;
        r.x = fmaxf((v[i].x - mu) * rstd * gg.x + bb.x, 0.f);
        r.y = fmaxf((v[i].y - mu) * rstd * gg.y + bb.y, 0.f);
        r.z = fmaxf((v[i].z - mu) * rstd * gg.z + bb.z, 0.f);
        r.w = fmaxf((v[i].w - mu) * rstd * gg.w + bb.w, 0.f);
        o[lane + 32 * i] = r;
    }
}

// ---------------- launch ----------------

extern "C" void kernel_launch(void* const* d_in, const int* in_sizes, int n_in,
                              void* d_out, int out_size)
{
    (void)in_sizes; (void)n_in; (void)out_size;
    const float* node   = (const float*)d_in[0];
    const float* adj    = (const float*)d_in[1];
    const float* conv_w = (const float*)d_in[2];
    const float* conv_b = (const float*)d_in[3];
    const float* mlp_w  = (const float*)d_in[4];
    const float* mlp_b  = (const float*)d_in[5];
    const float* ln_g   = (const float*)d_in[6];
    const float* ln_b   = (const float*)d_in[7];
    const float* lin_w  = (const float*)d_in[8];
    const float* lin_b  = (const float*)d_in[9];
    float* out = (float*)d_out;

    float *pX, *pY, *pZ;
    uint2 *pW;
    cudaGetSymbolAddress((void**)&pX, g_X);
    cudaGetSymbolAddress((void**)&pY, g_Y);
    cudaGetSymbolAddress((void**)&pZ, g_Z);
    cudaGetSymbolAddress((void**)&pW, g_Wsplit);

    // raise dynamic smem cap for the GEMM (54.3KB > 48KB default); idempotent host call
    cudaFuncSetAttribute(gemm_tc_kernel, cudaFuncAttributeMaxDynamicSharedMemorySize, SMEM_GEMM);

    // pre-split all weights into tf32 {hi, lo}
    wsplit_kernel<<<(3 * WMAT) / 256, 256>>>(conv_w, pW + W_CONV_OFF, 3 * WMAT);
    wsplit_kernel<<<(3 * WMAT) / 256, 256>>>(mlp_w,  pW + W_MLP_OFF,  3 * WMAT);
    wsplit_kernel<<<WMAT / 256, 256>>>(lin_w, pW + W_LIN_OFF, WMAT);

    // sparse preprocessing (deterministic, atomic-free, single pass over A)
    stats_compact_kernel<<<dim3(64, 16), 128>>>(adj);
    dinv_kernel<<<32, 256>>>(adj);
    scan_kernel<<<1, 1024>>>();
    choff_kernel<<<32, 256>>>();
    fill_kernel<<<dim3(64, 16), 128>>>(adj);

    dim3 ggrid(4, 64);   // N tiles x M tiles
    for (int l = 0; l < 3; l++) {
        const float* xin = (l == 0) ? node : pX;
        gemm_tc_kernel<<<ggrid, 256, SMEM_GEMM>>>(xin, pW + W_CONV_OFF + (size_t)l * WMAT, nullptr, pY);
        spmm_kernel<<<1024, 256>>>(pY, conv_b + (size_t)l * HH, pZ);
        gemm_tc_kernel<<<ggrid, 256, SMEM_GEMM>>>(pZ, pW + W_MLP_OFF + (size_t)l * WMAT, mlp_b + (size_t)l * HH, pY);
        ln_relu_kernel<<<1024, 256>>>(pY, ln_g + (size_t)l * HH, ln_b + (size_t)l * HH, pX);
    }
    gemm_tc_kernel<<<ggrid, 256, SMEM_GEMM>>>(pX, pW + W_LIN_OFF, lin_b, out);
}

// round 17
// speedup vs baseline: 1.3829x; 1.3829x over previous
#include <cuda_runtime.h>
#include <cuda_bf16.h>
#include <cstdint>

// GCNDecoder: x' = relu(LN(Ahat^T (x W_conv) + b_conv) W_mlp + b_mlp)) x3, then x W_lin + b_lin
// N=8192 nodes, H=512 features, 3 layers, O=512.

#define NND   8192
#define HH    512
#define CHUNKS 16
#define RPC   (NND / CHUNKS)     // 512 rows per chunk
#define MAXNNZ (1 << 22)
#define CAP   32

#define PA (NND * 256)           // activation plane stride (u32 elems): [m][kp]
#define PW (256 * 512)           // weight plane stride (u32 elems): [kp][n] = 2^17

// ---------------- device scratch (no allocations allowed) ----------------
__device__ float g_dinv[NND];
__device__ float g_selfc[NND];
__device__ float g_dsum2[CHUNKS * NND];
__device__ int   g_cnt2[CHUNKS * NND];
__device__ int   g_tot[NND];
__device__ int   g_rowptr[NND + 1];
__device__ int   g_choff[CHUNKS * NND];
__device__ __align__(16) uint2 g_pack[CHUNKS * NND * CAP];
__device__ int   g_cols[MAXNNZ];
__device__ float g_vals[MAXNNZ];
__device__ __align__(16) uint32_t g_W2[7 * 2 * PW];   // weights: per matrix 2 bf16-split planes
__device__ __align__(16) uint32_t g_A2[2 * PA];       // activations: 2 bf16-split planes
__device__ float g_Y[NND * HH];                       // f32 GEMM outputs

// ---------------- bf16 2-level split helpers ----------------
// x = h0 + h1 + r, h0=bf16(x), h1=bf16(x-h0), |r| ~ 2^-18|x|.
// For a k-pair (xe=even k, xo=odd k): returns {plane0 word, plane1 word},
// each word = (bf16(xo)<<16) | bf16(xe)  (lower half = smaller k, per mma layout).
__device__ __forceinline__ uint2 split2(float xe, float xo) {
    __nv_bfloat16 e0 = __float2bfloat16_rn(xe);
    __nv_bfloat16 o0 = __float2bfloat16_rn(xo);
    __nv_bfloat16 e1 = __float2bfloat16_rn(xe - __bfloat162float(e0));
    __nv_bfloat16 o1 = __float2bfloat16_rn(xo - __bfloat162float(o0));
    uint32_t w0 = ((uint32_t)__bfloat16_as_ushort(o0) << 16) | (uint32_t)__bfloat16_as_ushort(e0);
    uint32_t w1 = ((uint32_t)__bfloat16_as_ushort(o1) << 16) | (uint32_t)__bfloat16_as_ushort(e1);
    return make_uint2(w0, w1);
}

// weights [nmat][512][512] f32 -> per matrix: 2 planes [256][512] u32
__global__ void wsplit2_kernel(const float* __restrict__ src, uint32_t* __restrict__ dst, int nmat) {
    int i = blockIdx.x * blockDim.x + threadIdx.x;
    if (i >= nmat * PW) return;
    int mat = i >> 17;
    int r = i & (PW - 1);
    int kp = r >> 9, n = r & 511;
    const float* s = src + (size_t)mat * 262144;
    float xe = s[(2 * kp) * 512 + n];
    float xo = s[(2 * kp + 1) * 512 + n];
    uint2 w = split2(xe, xo);
    uint32_t* d = dst + (size_t)mat * (2 * PW);
    d[r] = w.x;
    d[PW + r] = w.y;
}

// node [8192][512] f32 -> activation planes
__global__ void nsplit_kernel(const float* __restrict__ src, uint32_t* __restrict__ dst) {
    int i = blockIdx.x * blockDim.x + threadIdx.x;   // [0, NND*256)
    int m = i >> 8, kp = i & 255;
    float2 v = *(const float2*)(src + (size_t)m * 512 + 2 * kp);
    uint2 s = split2(v.x, v.y);
    dst[i] = s.x;
    dst[PA + i] = s.y;
}

// ---------------- preprocessing ----------------

// Single pass over A; 4x unrolled loads (independent, front-issued) for MLP.
__global__ void stats_compact_kernel(const float* __restrict__ A) {
    int t = blockIdx.x * 128 + threadIdx.x;
    int c = blockIdx.y;
    int s0 = c * RPC;
    const float* p = A + (size_t)s0 * NND + t;
    uint2* cell = g_pack + (size_t)(c * NND + t) * CAP;
    float sum = 0.f;
    int cnt = 0;
    for (int i = 0; i < RPC; i += 4) {
        float v0 = p[(size_t)(i + 0) * NND];
        float v1 = p[(size_t)(i + 1) * NND];
        float v2 = p[(size_t)(i + 2) * NND];
        float v3 = p[(size_t)(i + 3) * NND];
        if (v0 > 0.f) { sum += v0; if (cnt < CAP) cell[cnt] = make_uint2((unsigned)(s0 + i + 0), __float_as_uint(v0)); cnt++; }
        if (v1 > 0.f) { sum += v1; if (cnt < CAP) cell[cnt] = make_uint2((unsigned)(s0 + i + 1), __float_as_uint(v1)); cnt++; }
        if (v2 > 0.f) { sum += v2; if (cnt < CAP) cell[cnt] = make_uint2((unsigned)(s0 + i + 2), __float_as_uint(v2)); cnt++; }
        if (v3 > 0.f) { sum += v3; if (cnt < CAP) cell[cnt] = make_uint2((unsigned)(s0 + i + 3), __float_as_uint(v3)); cnt++; }
    }
    g_dsum2[c * NND + t] = sum;
    g_cnt2[c * NND + t] = cnt;
}

__global__ void dinv_kernel(const float* __restrict__ A) {
    int t = blockIdx.x * blockDim.x + threadIdx.x;
    if (t >= NND) return;
    float ds = 0.f; int tot = 0;
#pragma unroll
    for (int c = 0; c < CHUNKS; c++) {
        ds += g_dsum2[c * NND + t];
        tot += g_cnt2[c * NND + t];
    }
    float d = A[(size_t)t * NND + t];
    float sl = (d > 0.f) ? 0.f : 1.f;
    float deg = ds + sl;
    float dv = (deg > 0.f) ? rsqrtf(deg) : 0.f;
    g_dinv[t] = dv;
    g_selfc[t] = sl * dv * dv;
    g_tot[t] = tot;
}

__global__ void scan_kernel() {
    int tid = threadIdx.x;
    int base = tid * 8;
    int loc[8]; int s = 0;
#pragma unroll
    for (int i = 0; i < 8; i++) { int v = g_tot[base + i]; loc[i] = s; s += v; }
    int lane = tid & 31, wid = tid >> 5;
    int val = s;
#pragma unroll
    for (int off = 1; off < 32; off <<= 1) {
        int n = __shfl_up_sync(0xffffffffu, val, off);
        if (lane >= off) val += n;
    }
    __shared__ int wsum[32];
    if (lane == 31) wsum[wid] = val;
    __syncthreads();
    if (wid == 0) {
        int w = wsum[lane];
#pragma unroll
        for (int off = 1; off < 32; off <<= 1) {
            int n = __shfl_up_sync(0xffffffffu, w, off);
            if (lane >= off) w += n;
        }
        wsum[lane] = w;
    }
    __syncthreads();
    int warpoff = (wid == 0) ? 0 : wsum[wid - 1];
    int excl = warpoff + (val - s);
#pragma unroll
    for (int i = 0; i < 8; i++) g_rowptr[base + i] = excl + loc[i];
    if (tid == 1023) g_rowptr[NND] = excl + s;
}

__global__ void choff_kernel() {
    int t = blockIdx.x * blockDim.x + threadIdx.x;
    if (t >= NND) return;
    int run = g_rowptr[t];
#pragma unroll
    for (int c = 0; c < CHUNKS; c++) {
        g_choff[c * NND + t] = run;
        run += g_cnt2[c * NND + t];
    }
}

__global__ void fill_kernel(const float* __restrict__ A) {
    int t = blockIdx.x * 128 + threadIdx.x;
    int c = blockIdx.y;
    int cell_idx = c * NND + t;
    int cnt = g_cnt2[cell_idx];
    int pos = g_choff[cell_idx];
    float dt = g_dinv[t];
    if (cnt <= CAP) {
        const uint2* cell = g_pack + (size_t)cell_idx * CAP;
        for (int j = 0; j < cnt; j++) {
            uint2 e = cell[j];
            int s = (int)e.x;
            if (pos < MAXNNZ) {
                g_cols[pos] = s;
                g_vals[pos] = __uint_as_float(e.y) * __ldg(&g_dinv[s]) * dt;
            }
            pos++;
        }
    } else {
        int s0 = c * RPC;
        const float* p = A + (size_t)s0 * NND + t;
        for (int i = 0; i < RPC; i++) {
            float v = p[(size_t)i * NND];
            if (v > 0.f) {
                if (pos < MAXNNZ) {
                    int s = s0 + i;
                    g_cols[pos] = s;
                    g_vals[pos] = v * __ldg(&g_dinv[s]) * dt;
                }
                pos++;
            }
        }
    }
}

// ---------------- tensor-core GEMM (3-term bf16x2): C = A @ B (+bias) ----------------
// 128x128 tile, BK=16, 256 threads = 8 warps (2x4), warp tile 64x32.
// Both operands pre-split into 2 bf16 planes; C += A0B0 + A0B1 + A1B0 via
// mma.m16n8k16.bf16 (3 mma per 16x8x16 tile vs 6 tf32-mma equivalents).
// Single barrier per slab. Static smem 42KB, 2 CTAs/SM.

#define ASTR 12                  // A plane row stride (8 kp used + 4 pad): conflict-free
#define BSTR 136                 // B plane row stride (128 n + 8 pad): conflict-free
#define A_PL (128 * ASTR)        // 1536 u32 per A plane-slab
#define B_PL (8 * BSTR)          // 1088 u32 per B plane-slab

__device__ __forceinline__ void mma_bf16(float* c, const uint32_t* a, const uint32_t* b) {
    asm volatile(
        "mma.sync.aligned.m16n8k16.row.col.f32.bf16.bf16.f32 "
        "{%0,%1,%2,%3}, {%4,%5,%6,%7}, {%8,%9}, {%0,%1,%2,%3};"
        : "+f"(c[0]), "+f"(c[1]), "+f"(c[2]), "+f"(c[3])
        : "r"(a[0]), "r"(a[1]), "r"(a[2]), "r"(a[3]), "r"(b[0]), "r"(b[1]));
}

#define CP_ASYNC16(dst32, src) \
    asm volatile("cp.async.ca.shared.global [%0], [%1], 16;" :: "r"(dst32), "l"(src))
#define CP_COMMIT() asm volatile("cp.async.commit_group;")
#define CP_WAIT0()  asm volatile("cp.async.wait_group 0;")

__global__ __launch_bounds__(256, 2) void gemm_bf16_kernel(
    const uint32_t* __restrict__ A2, const uint32_t* __restrict__ B2,
    const float* __restrict__ bias, float* __restrict__ C)
{
    __shared__ __align__(16) uint32_t As[2][2][A_PL];   // [buf][plane][m*ASTR+kp]
    __shared__ __align__(16) uint32_t Bs[2][2][B_PL];   // [buf][plane][kp*BSTR+n]

    const int tid = threadIdx.x;
    const int lane = tid & 31;
    const int warp = tid >> 5;
    const int gid = lane >> 2;    // 0..7
    const int tig = lane & 3;     // 0..3
    const int wm = warp >> 2;     // m offset wm*64
    const int wn = warp & 3;      // n offset wn*32

    const uint32_t* Ab = A2 + (size_t)blockIdx.y * 128 * 256;
    const uint32_t* Bb = B2 + blockIdx.x * 128;

    const int amrow = tid >> 1, ac = tid & 1;
    const int brow = tid >> 5, bc = tid & 31;

    uint32_t a_dst[2], b_dst[2];
#pragma unroll
    for (int r = 0; r < 2; r++) {
        a_dst[r] = (uint32_t)__cvta_generic_to_shared(&As[0][r][amrow * ASTR + ac * 4]);
        b_dst[r] = (uint32_t)__cvta_generic_to_shared(&Bs[0][r][brow * BSTR + bc * 4]);
    }
    const uint32_t abuf1 = (uint32_t)(2 * A_PL * 4);
    const uint32_t bbuf1 = (uint32_t)(2 * B_PL * 4);
    const uint32_t* aSrc0 = Ab + (size_t)0 * PA + amrow * 256 + ac * 4;
    const uint32_t* aSrc1 = Ab + (size_t)1 * PA + amrow * 256 + ac * 4;
    const uint32_t* bSrc0 = Bb + (size_t)0 * PW + brow * 512 + bc * 4;
    const uint32_t* bSrc1 = Bb + (size_t)1 * PW + brow * 512 + bc * 4;

    float acc[4][4][4];
#pragma unroll
    for (int i = 0; i < 4; i++)
#pragma unroll
        for (int j = 0; j < 4; j++)
#pragma unroll
            for (int q = 0; q < 4; q++) acc[i][j][q] = 0.f;

    CP_ASYNC16(a_dst[0], aSrc0);
    CP_ASYNC16(a_dst[1], aSrc1);
    CP_ASYNC16(b_dst[0], bSrc0);
    CP_ASYNC16(b_dst[1], bSrc1);
    CP_COMMIT();

    const int NT = 512 / 16;   // 32 slabs
    for (int t = 0; t < NT; t++) {
        CP_WAIT0();
        __syncthreads();

        if (t + 1 < NT) {
            uint32_t dA = ((t + 1) & 1) ? abuf1 : 0;
            uint32_t dB = ((t + 1) & 1) ? bbuf1 : 0;
            int ka = (t + 1) * 8;
            int kb = (t + 1) * 4096;
            CP_ASYNC16(a_dst[0] + dA, aSrc0 + ka);
            CP_ASYNC16(a_dst[1] + dA, aSrc1 + ka);
            CP_ASYNC16(b_dst[0] + dB, bSrc0 + kb);
            CP_ASYNC16(b_dst[1] + dB, bSrc1 + kb);
            CP_COMMIT();
        }

        const int buf = t & 1;
        const uint32_t* B0 = Bs[buf][0];
        const uint32_t* B1 = Bs[buf][1];
        const uint32_t* A0 = As[buf][0];
        const uint32_t* A1 = As[buf][1];

        uint32_t bf0[4][2], bf1[4][2];
#pragma unroll
        for (int ni = 0; ni < 4; ni++) {
            int n = wn * 32 + ni * 8 + gid;
            bf0[ni][0] = B0[tig * BSTR + n];
            bf0[ni][1] = B0[(tig + 4) * BSTR + n];
            bf1[ni][0] = B1[tig * BSTR + n];
            bf1[ni][1] = B1[(tig + 4) * BSTR + n];
        }
#pragma unroll
        for (int mi = 0; mi < 4; mi++) {
            int m = wm * 64 + mi * 16 + gid;
            uint32_t a0[4], a1[4];
            a0[0] = A0[m * ASTR + tig];
            a0[1] = A0[(m + 8) * ASTR + tig];
            a0[2] = A0[m * ASTR + tig + 4];
            a0[3] = A0[(m + 8) * ASTR + tig + 4];
            a1[0] = A1[m * ASTR + tig];
            a1[1] = A1[(m + 8) * ASTR + tig];
            a1[2] = A1[m * ASTR + tig + 4];
            a1[3] = A1[(m + 8) * ASTR + tig + 4];
#pragma unroll
            for (int ni = 0; ni < 4; ni++) {
                mma_bf16(acc[mi][ni], a0, bf0[ni]);   // A0*B0
                mma_bf16(acc[mi][ni], a0, bf1[ni]);   // A0*B1
                mma_bf16(acc[mi][ni], a1, bf0[ni]);   // A1*B0
            }
        }
    }

    // epilogue
    float bb[4][2];
#pragma unroll
    for (int ni = 0; ni < 4; ni++) {
        int col = wn * 32 + ni * 8 + tig * 2;
        if (bias) {
            bb[ni][0] = bias[blockIdx.x * 128 + col];
            bb[ni][1] = bias[blockIdx.x * 128 + col + 1];
        } else {
            bb[ni][0] = 0.f; bb[ni][1] = 0.f;
        }
    }
    float* Cb = C + (size_t)blockIdx.y * 128 * 512 + blockIdx.x * 128;
#pragma unroll
    for (int mi = 0; mi < 4; mi++) {
#pragma unroll
        for (int ni = 0; ni < 4; ni++) {
            int row0 = wm * 64 + mi * 16 + gid;
            int col = wn * 32 + ni * 8 + tig * 2;
            float2 v0 = { acc[mi][ni][0] + bb[ni][0], acc[mi][ni][1] + bb[ni][1] };
            float2 v1 = { acc[mi][ni][2] + bb[ni][0], acc[mi][ni][3] + bb[ni][1] };
            *(float2*)(Cb + (size_t)row0 * 512 + col) = v0;
            *(float2*)(Cb + (size_t)(row0 + 8) * 512 + col) = v1;
        }
    }
}

// ---------------- split-emit helper for epilogues ----------------
__device__ __forceinline__ void emit_split(uint32_t* outr, int kp0, float4 a) {
    uint2 sxy = split2(a.x, a.y);
    uint2 szw = split2(a.z, a.w);
    *(uint2*)(outr + kp0) = make_uint2(sxy.x, szw.x);
    *(uint2*)(outr + PA + kp0) = make_uint2(sxy.y, szw.y);
}

// ---------------- SpMM: writes split activation planes ----------------
__global__ void spmm_kernel(const float* __restrict__ Y,
                            const float* __restrict__ bias,
                            uint32_t* __restrict__ Aout)
{
    int gw = (blockIdx.x * blockDim.x + threadIdx.x) >> 5;
    int lane = threadIdx.x & 31;
    if (gw >= NND) return;
    int beg = __ldg(&g_rowptr[gw]), end = __ldg(&g_rowptr[gw + 1]);
    const float4* Y4 = (const float4*)Y;

    float sc = g_selfc[gw];
    const float4* xr = Y4 + (size_t)gw * 128 + lane;
    float4 s0 = __ldg(xr), s1 = __ldg(xr + 32), s2 = __ldg(xr + 64), s3 = __ldg(xr + 96);
    const float4* b4 = (const float4*)bias;
    float4 b0 = __ldg(b4 + lane), b1 = __ldg(b4 + lane + 32),
           b2 = __ldg(b4 + lane + 64), b3 = __ldg(b4 + lane + 96);

    float4 a0 = {0,0,0,0}, a1 = a0, a2 = a0, a3 = a0;
    int k = beg;
    for (; k + 1 < end; k += 2) {
        int sA = g_cols[k],   sB = g_cols[k + 1];
        float wA = g_vals[k], wB = g_vals[k + 1];
        const float4* yA = Y4 + (size_t)sA * 128 + lane;
        const float4* yB = Y4 + (size_t)sB * 128 + lane;
        float4 u0 = __ldg(yA), u1 = __ldg(yA + 32), u2 = __ldg(yA + 64), u3 = __ldg(yA + 96);
        float4 t0 = __ldg(yB), t1 = __ldg(yB + 32), t2 = __ldg(yB + 64), t3 = __ldg(yB + 96);
        a0.x += wA * u0.x; a0.y += wA * u0.y; a0.z += wA * u0.z; a0.w += wA * u0.w;
        a1.x += wA * u1.x; a1.y += wA * u1.y; a1.z += wA * u1.z; a1.w += wA * u1.w;
        a2.x += wA * u2.x; a2.y += wA * u2.y; a2.z += wA * u2.z; a2.w += wA * u2.w;
        a3.x += wA * u3.x; a3.y += wA * u3.y; a3.z += wA * u3.z; a3.w += wA * u3.w;
        a0.x += wB * t0.x; a0.y += wB * t0.y; a0.z += wB * t0.z; a0.w += wB * t0.w;
        a1.x += wB * t1.x; a1.y += wB * t1.y; a1.z += wB * t1.z; a1.w += wB * t1.w;
        a2.x += wB * t2.x; a2.y += wB * t2.y; a2.z += wB * t2.z; a2.w += wB * t2.w;
        a3.x += wB * t3.x; a3.y += wB * t3.y; a3.z += wB * t3.z; a3.w += wB * t3.w;
    }
    if (k < end) {
        int s = g_cols[k];
        float w = g_vals[k];
        const float4* yr = Y4 + (size_t)s * 128 + lane;
        float4 v0 = __ldg(yr), v1 = __ldg(yr + 32), v2 = __ldg(yr + 64), v3 = __ldg(yr + 96);
        a0.x += w * v0.x; a0.y += w * v0.y; a0.z += w * v0.z; a0.w += w * v0.w;
        a1.x += w * v1.x; a1.y += w * v1.y; a1.z += w * v1.z; a1.w += w * v1.w;
        a2.x += w * v2.x; a2.y += w * v2.y; a2.z += w * v2.z; a2.w += w * v2.w;
        a3.x += w * v3.x; a3.y += w * v3.y; a3.z += w * v3.z; a3.w += w * v3.w;
    }
    a0.x += sc * s0.x + b0.x; a0.y += sc * s0.y + b0.y; a0.z += sc * s0.z + b0.z; a0.w += sc * s0.w + b0.w;
    a1.x += sc * s1.x + b1.x; a1.y += sc * s1.y + b1.y; a1.z += sc * s1.z + b1.z; a1.w += sc * s1.w + b1.w;
    a2.x += sc * s2.x + b2.x; a2.y += sc * s2.y + b2.y; a2.z += sc * s2.z + b2.z; a2.w += sc * s2.w + b2.w;
    a3.x += sc * s3.x + b3.x; a3.y += sc * s3.y + b3.y; a3.z += sc * s3.z + b3.z; a3.w += sc * s3.w + b3.w;

    uint32_t* outr = Aout + (size_t)gw * 256;
    emit_split(outr, 2 * lane,        a0);
    emit_split(outr, 2 * (lane + 32), a1);
    emit_split(outr, 2 * (lane + 64), a2);
    emit_split(outr, 2 * (lane + 96), a3);
}

// ---------------- LayerNorm + ReLU: writes split activation planes ----------------
__global__ void ln_relu_kernel(const float* __restrict__ Xin,
                               const float* __restrict__ g,
                               const float* __restrict__ b,
                               uint32_t* __restrict__ Aout)
{
    int gw = (blockIdx.x * blockDim.x + threadIdx.x) >> 5;
    int lane = threadIdx.x & 31;
    if (gw >= NND) return;
    const float4* xr = (const float4*)Xin + (size_t)gw * 128;
    float4 v[4];
    float s = 0.f;
#pragma unroll
    for (int i = 0; i < 4; i++) {
        v[i] = xr[lane + 32 * i];
        s += v[i].x + v[i].y + v[i].z + v[i].w;
    }
#pragma unroll
    for (int off = 16; off; off >>= 1) s += __shfl_xor_sync(0xffffffffu, s, off);
    float mu = s * (1.f / 512.f);
    float var = 0.f;
#pragma unroll
    for (int i = 0; i < 4; i++) {
        float dx = v[i].x - mu, dy = v[i].y - mu, dz = v[i].z - mu, dw = v[i].w - mu;
        var += dx * dx + dy * dy + dz * dz + dw * dw;
    }
#pragma unroll
    for (int off = 16; off; off >>= 1) var += __shfl_xor_sync(0xffffffffu, var, off);
    float rstd = rsqrtf(var * (1.f / 512.f) + 1e-5f);
    const float4* g4 = (const float4*)g;
    const float4* b4 = (const float4*)b;
    uint32_t* outr = Aout + (size_t)gw * 256;
#pragma unroll
    for (int i = 0; i < 4; i++) {
        float4 gg = g4[lane + 32 * i], bb = b4[lane + 32 * i];
        float4 r;
        r.x = fmaxf((v[i].x - mu) * rstd * gg.x + bb.x, 0.f);
        r.y = fmaxf((v[i].y - mu) * rstd * gg.y + bb.y, 0.f);
        r.z = fmaxf((v[i].z - mu) * rstd * gg.z + bb.z, 0.f);
        r.w = fmaxf((v[i].w - mu) * rstd * gg.w + bb.w, 0.f);
        emit_split(outr, 2 * (lane + 32 * i), r);
    }
}

// ---------------- launch ----------------

extern "C" void kernel_launch(void* const* d_in, const int* in_sizes, int n_in,
                              void* d_out, int out_size)
{
    (void)in_sizes; (void)n_in; (void)out_size;
    const float* node   = (const float*)d_in[0];
    const float* adj    = (const float*)d_in[1];
    const float* conv_w = (const float*)d_in[2];
    const float* conv_b = (const float*)d_in[3];
    const float* mlp_w  = (const float*)d_in[4];
    const float* mlp_b  = (const float*)d_in[5];
    const float* ln_g   = (const float*)d_in[6];
    const float* ln_b   = (const float*)d_in[7];
    const float* lin_w  = (const float*)d_in[8];
    const float* lin_b  = (const float*)d_in[9];
    float* out = (float*)d_out;

    float *pY;
    uint32_t *pW2, *pA2;
    cudaGetSymbolAddress((void**)&pY, g_Y);
    cudaGetSymbolAddress((void**)&pW2, g_W2);
    cudaGetSymbolAddress((void**)&pA2, g_A2);

    // pre-split weights (bf16 2-level planes) and node features
    wsplit2_kernel<<<(3 * PW) / 256, 256>>>(conv_w, pW2, 3);
    wsplit2_kernel<<<(3 * PW) / 256, 256>>>(mlp_w,  pW2 + (size_t)3 * 2 * PW, 3);
    wsplit2_kernel<<<PW / 256, 256>>>(lin_w, pW2 + (size_t)6 * 2 * PW, 1);
    nsplit_kernel<<<(NND * 256) / 256, 256>>>(node, pA2);

    // sparse preprocessing (deterministic, atomic-free, single pass over A)
    stats_compact_kernel<<<dim3(64, 16), 128>>>(adj);
    dinv_kernel<<<32, 256>>>(adj);
    scan_kernel<<<1, 1024>>>();
    choff_kernel<<<32, 256>>>();
    fill_kernel<<<dim3(64, 16), 128>>>(adj);

    dim3 ggrid(4, 64);
    for (int l = 0; l < 3; l++) {
        gemm_bf16_kernel<<<ggrid, 256>>>(pA2, pW2 + (size_t)l * 2 * PW, nullptr, pY);
        spmm_kernel<<<1024, 256>>>(pY, conv_b + (size_t)l * HH, pA2);
        gemm_bf16_kernel<<<ggrid, 256>>>(pA2, pW2 + (size_t)(3 + l) * 2 * PW, mlp_b + (size_t)l * HH, pY);
        ln_relu_kernel<<<1024, 256>>>(pY, ln_g + (size_t)l * HH, ln_b + (size_t)l * HH, pA2);
    }
    gemm_bf16_kernel<<<ggrid, 256>>>(pA2, pW2 + (size_t)6 * 2 * PW, lin_b, out);
}